// round 2
// baseline (speedup 1.0000x reference)
#include <cuda_runtime.h>
#include <cuda_bf16.h>

// Local2d: out[b,o,x,y] = sum_{i,kh,kw} weight[x,y,o,i,kh,kw] * x_pad[b,i,x+kh-1,y+kw-1] + bias[o,x,y]
// B=32, C_in=64, C_out=64, H=W=32, K=3, pad=1, stride=1 -> h_out=w_out=32.
// One CTA per spatial position: GEMM D[32b x 64o] = P[32b x 576k] * W[576k x 64o].

#define B_   32
#define CI_  64
#define CO_  64
#define H_   32
#define W_   32
#define KTOT 576          // CI_*9
#define KC   64           // K chunk
#define PS_STRIDE 33      // padded (conflict-free)
#define WS_STRIDE 65      // padded (conflict-free)
#define NTHREADS 128

#define SMEM_FLOATS (KTOT * PS_STRIDE + CO_ * WS_STRIDE)
#define SMEM_BYTES  (SMEM_FLOATS * 4)

__global__ __launch_bounds__(NTHREADS, 2)
void local2d_kernel(const float* __restrict__ x,
                    const float* __restrict__ wgt,
                    const float* __restrict__ bias,
                    float* __restrict__ out)
{
    extern __shared__ float sm[];
    float* Ps = sm;                       // [KTOT][PS_STRIDE] : patches, k-major
    float* Ws = sm + KTOT * PS_STRIDE;    // [CO_][WS_STRIDE]  : weight chunk, o-major

    const int pos = blockIdx.x;           // pos = x0*32 + y0
    const int x0  = pos >> 5;
    const int y0  = pos & 31;
    const int t   = threadIdx.x;

    // ---- Load all patches for this position into smem (done once) ----
    // idx enumerates (b, i, kh); each thread writes the 3 kw values of that row triple.
    for (int idx = t; idx < B_ * CI_ * 3; idx += NTHREADS) {
        int b   = idx / (CI_ * 3);
        int rem = idx - b * (CI_ * 3);
        int i   = rem / 3;
        int kh  = rem - i * 3;
        int h   = x0 + kh - 1;
        bool hok = ((unsigned)h < (unsigned)H_);
        const float* xrow = x + (((size_t)(b * CI_ + i) * H_ + h) * W_);
        int kbase = i * 9 + kh * 3;
        #pragma unroll
        for (int kw = 0; kw < 3; kw++) {
            int wc = y0 + kw - 1;
            float v = (hok && (unsigned)wc < (unsigned)W_) ? xrow[wc] : 0.0f;
            Ps[(kbase + kw) * PS_STRIDE + b] = v;
        }
    }

    const float* wpos = wgt + (size_t)pos * CO_ * KTOT;   // W[o][k] for this position

    // micro-tile assignment: 4 batch x 4 cout per thread
    const int tb = t & 7;     // b = tb*4 + j
    const int to = t >> 3;    // o = to*4 + j

    float acc[4][4];
    #pragma unroll
    for (int bi = 0; bi < 4; bi++)
        #pragma unroll
        for (int oi = 0; oi < 4; oi++)
            acc[bi][oi] = 0.0f;

    // ---- K loop: stream weight chunks through smem ----
    for (int kc = 0; kc < KTOT; kc += KC) {
        __syncthreads();   // previous chunk fully consumed (also orders patch writes on iter 0)

        // load W[o][kc..kc+63] -> Ws[o][0..63]; 1024 float4 loads, coalesced along k
        #pragma unroll
        for (int f = t; f < CO_ * (KC / 4); f += NTHREADS) {
            int o  = f >> 4;
            int kq = f & 15;
            float4 v = *(const float4*)(wpos + (size_t)o * KTOT + kc + kq * 4);
            float* dst = Ws + o * WS_STRIDE + kq * 4;
            dst[0] = v.x; dst[1] = v.y; dst[2] = v.z; dst[3] = v.w;
        }
        __syncthreads();

        #pragma unroll 4
        for (int k = 0; k < KC; k++) {
            const int kk = kc + k;
            float p[4], wv[4];
            #pragma unroll
            for (int j = 0; j < 4; j++)
                p[j] = Ps[kk * PS_STRIDE + tb * 4 + j];
            #pragma unroll
            for (int j = 0; j < 4; j++)
                wv[j] = Ws[(to * 4 + j) * WS_STRIDE + k];
            #pragma unroll
            for (int bi = 0; bi < 4; bi++)
                #pragma unroll
                for (int oi = 0; oi < 4; oi++)
                    acc[bi][oi] = fmaf(p[bi], wv[oi], acc[bi][oi]);
        }
    }

    // ---- Epilogue: add bias, store ----
    float bv[4];
    #pragma unroll
    for (int oi = 0; oi < 4; oi++)
        bv[oi] = bias[(to * 4 + oi) * (H_ * W_) + pos];

    #pragma unroll
    for (int bi = 0; bi < 4; bi++) {
        int b = tb * 4 + bi;
        #pragma unroll
        for (int oi = 0; oi < 4; oi++) {
            int o = to * 4 + oi;
            out[((size_t)(b * CO_ + o)) * (H_ * W_) + pos] = acc[bi][oi] + bv[oi];
        }
    }
}

extern "C" void kernel_launch(void* const* d_in, const int* in_sizes, int n_in,
                              void* d_out, int out_size)
{
    const float* x    = (const float*)d_in[0];
    const float* wgt  = (const float*)d_in[1];
    const float* bias = (const float*)d_in[2];
    float* out        = (float*)d_out;

    cudaFuncSetAttribute(local2d_kernel,
                         cudaFuncAttributeMaxDynamicSharedMemorySize, SMEM_BYTES);

    dim3 grid(H_ * W_);      // 1024 positions
    dim3 block(NTHREADS);
    local2d_kernel<<<grid, block, SMEM_BYTES>>>(x, wgt, bias, out);
}

// round 4
// speedup vs baseline: 1.0585x; 1.0585x over previous
#include <cuda_runtime.h>
#include <cstdint>
#include <cstddef>

// Local2d: out[b,o,x,y] = sum_{i,kh,kw} weight[x,y,o,i,kh,kw] * x_pad[b,i,x+kh-1,y+kw-1] + bias[o,x,y]
// B=32, C_in=64, C_out=64, H=W=32, K=3, pad=1 -> 32x32 positions.
// One CTA per position: D[32b x 64o] = P[32b x 576k] * W[576k x 64o].
// Packed fp32 (fma.rn.f32x2) over batch pairs; weights duplicated (w,w) in smem.

#define B_   32
#define CI_  64
#define CO_  64
#define H_   32
#define W_   32
#define KTOT 576
#define KC   32
#define NCHUNK (KTOT / KC)        // 18
#define PS_STRIDE 36              // floats per patch k-row (multiple of 4 -> 16B rows)
#define WD_STRIDE 132             // floats per dup-weight k-row (528B; conflict-free phases)
#define NTHREADS 128

#define PS_FLOATS (KTOT * PS_STRIDE)          // 20736
#define WD_FLOATS (KC * WD_STRIDE)            // 4224
#define SMEM_BYTES ((PS_FLOATS + WD_FLOATS) * 4)   // 99840 B -> 2 CTAs/SM

__global__ __launch_bounds__(NTHREADS, 2)
void local2d_kernel(const float* __restrict__ x,
                    const float* __restrict__ wgt,
                    const float* __restrict__ bias,
                    float* __restrict__ out)
{
    extern __shared__ float sm[];
    float* Ps = sm;                       // [KTOT][PS_STRIDE] patches, k-major
    // Wd: [KC][WD_STRIDE], entry for o at word 2*o: (w,w) duplicated pair

    const int pos = blockIdx.x;
    const int x0  = pos >> 5;
    const int y0  = pos & 31;
    const int t   = threadIdx.x;

    // shared-space base address for asm ld/st
    uint32_t smemBase;
    asm("{ .reg .u64 tt; cvta.to.shared.u64 tt, %1; cvt.u32.u64 %0, tt; }"
        : "=r"(smemBase) : "l"(sm));
    const uint32_t PsBase = smemBase;
    const uint32_t WdBase = smemBase + PS_FLOATS * 4;

    // ---- patch prologue: all 576 k-rows of 32 b values ----
    for (int idx = t; idx < B_ * CI_ * 3; idx += NTHREADS) {
        int b   = idx / (CI_ * 3);
        int rem = idx - b * (CI_ * 3);
        int i   = rem / 3;
        int kh  = rem - i * 3;
        int h   = x0 + kh - 1;
        bool hok = ((unsigned)h < (unsigned)H_);
        const float* xrow = x + (((size_t)(b * CI_ + i) * H_ + h) * W_);
        int kbase = i * 9 + kh * 3;
        #pragma unroll
        for (int kw = 0; kw < 3; kw++) {
            int wc = y0 + kw - 1;
            float v = (hok && (unsigned)wc < (unsigned)W_) ? xrow[wc] : 0.0f;
            Ps[(kbase + kw) * PS_STRIDE + b] = v;
        }
    }

    const float* wpos = wgt + (size_t)pos * CO_ * KTOT;  // W[o][k], k contiguous

    // staging assignment: thread handles k = t&31 (within chunk), o-quads oq0+4i
    const int kk  = t & 31;
    const int oq0 = t >> 5;      // 0..3

    // compute tile: 4 batch (2 packed pairs) x 4 cout
    const int tb = t & 7;        // b base = tb*4
    const int to = t >> 3;       // o base = to*4   (0..15)

    uint64_t acc[2][4];
    #pragma unroll
    for (int a = 0; a < 2; a++)
        #pragma unroll
        for (int o = 0; o < 4; o++)
            acc[a][o] = 0ull;

    // stage chunk 0 (coalesced: lanes span 32 consecutive k, same o)
    float wst[4][4];
    #pragma unroll
    for (int i = 0; i < 4; i++) {
        int oq = oq0 + 4 * i;
        #pragma unroll
        for (int j = 0; j < 4; j++)
            wst[i][j] = wpos[(size_t)(oq * 4 + j) * KTOT + kk];
    }

    const uint32_t pRead0 = PsBase + (uint32_t)tb * 16;   // + k*PS_STRIDE*4
    const uint32_t wRead0 = WdBase + (uint32_t)to * 32;   // + k*WD_STRIDE*4
    const uint32_t sRow   = WdBase + (uint32_t)kk * (WD_STRIDE * 4);

    for (int c = 0; c < NCHUNK; c++) {
        __syncthreads();   // prev chunk consumed (iter0: patches ordered too)

        // dup-store staged chunk: Wd[kk][o] = (w,w)
        #pragma unroll
        for (int i = 0; i < 4; i++) {
            uint32_t a0 = sRow + (uint32_t)(oq0 + 4 * i) * 32;
            asm volatile("st.shared.v4.b32 [%0], {%1,%1,%2,%2};"
                         :: "r"(a0),      "f"(wst[i][0]), "f"(wst[i][1]));
            asm volatile("st.shared.v4.b32 [%0], {%1,%1,%2,%2};"
                         :: "r"(a0 + 16), "f"(wst[i][2]), "f"(wst[i][3]));
        }
        __syncthreads();

        // prefetch next chunk into regs (overlaps with compute below)
        if (c + 1 < NCHUNK) {
            const float* wnext = wpos + (c + 1) * KC;
            #pragma unroll
            for (int i = 0; i < 4; i++) {
                int oq = oq0 + 4 * i;
                #pragma unroll
                for (int j = 0; j < 4; j++)
                    wst[i][j] = wnext[(size_t)(oq * 4 + j) * KTOT + kk];
            }
        }

        // compute KC k-steps: 3 LDS.128 + 8 FFMA2 per k
        uint32_t pA = pRead0 + (uint32_t)(c * KC) * (PS_STRIDE * 4);
        uint32_t wA = wRead0;
        #pragma unroll 8
        for (int k = 0; k < KC; k++) {
            uint64_t p0, p1, w0, w1, w2, w3;
            asm("ld.shared.v2.b64 {%0,%1}, [%2];" : "=l"(p0), "=l"(p1) : "r"(pA));
            asm("ld.shared.v2.b64 {%0,%1}, [%2];" : "=l"(w0), "=l"(w1) : "r"(wA));
            asm("ld.shared.v2.b64 {%0,%1}, [%2];" : "=l"(w2), "=l"(w3) : "r"(wA + 16));
            asm("fma.rn.f32x2 %0, %1, %2, %0;" : "+l"(acc[0][0]) : "l"(p0), "l"(w0));
            asm("fma.rn.f32x2 %0, %1, %2, %0;" : "+l"(acc[0][1]) : "l"(p0), "l"(w1));
            asm("fma.rn.f32x2 %0, %1, %2, %0;" : "+l"(acc[0][2]) : "l"(p0), "l"(w2));
            asm("fma.rn.f32x2 %0, %1, %2, %0;" : "+l"(acc[0][3]) : "l"(p0), "l"(w3));
            asm("fma.rn.f32x2 %0, %1, %2, %0;" : "+l"(acc[1][0]) : "l"(p1), "l"(w0));
            asm("fma.rn.f32x2 %0, %1, %2, %0;" : "+l"(acc[1][1]) : "l"(p1), "l"(w1));
            asm("fma.rn.f32x2 %0, %1, %2, %0;" : "+l"(acc[1][2]) : "l"(p1), "l"(w2));
            asm("fma.rn.f32x2 %0, %1, %2, %0;" : "+l"(acc[1][3]) : "l"(p1), "l"(w3));
            pA += PS_STRIDE * 4;
            wA += WD_STRIDE * 4;
        }
    }

    // ---- epilogue: unpack pairs, add bias, store ----
    float bv[4];
    #pragma unroll
    for (int oi = 0; oi < 4; oi++)
        bv[oi] = bias[(to * 4 + oi) * (H_ * W_) + pos];

    #pragma unroll
    for (int bp = 0; bp < 2; bp++) {
        int b0 = tb * 4 + bp * 2;
        #pragma unroll
        for (int oi = 0; oi < 4; oi++) {
            float lo, hi;
            asm("mov.b64 {%0,%1}, %2;" : "=f"(lo), "=f"(hi) : "l"(acc[bp][oi]));
            int o = to * 4 + oi;
            out[((size_t)(b0 * CO_ + o)) * (H_ * W_) + pos]       = lo + bv[oi];
            out[((size_t)((b0 + 1) * CO_ + o)) * (H_ * W_) + pos] = hi + bv[oi];
        }
    }
}

extern "C" void kernel_launch(void* const* d_in, const int* in_sizes, int n_in,
                              void* d_out, int out_size)
{
    const float* x    = (const float*)d_in[0];
    const float* wgt  = (const float*)d_in[1];
    const float* bias = (const float*)d_in[2];
    float* out        = (float*)d_out;

    cudaFuncSetAttribute(local2d_kernel,
                         cudaFuncAttributeMaxDynamicSharedMemorySize, SMEM_BYTES);

    dim3 grid(H_ * W_);
    dim3 block(NTHREADS);
    local2d_kernel<<<grid, block, SMEM_BYTES>>>(x, wgt, bias, out);
}

// round 6
// speedup vs baseline: 1.3258x; 1.2525x over previous
#include <cuda_runtime.h>
#include <cstdint>
#include <cstddef>

// Local2d via mma.sync tf32 (m16n8k8): per position GEMM
//   D[64o x 32b] = W[64o x 576k] * P[576k x 32b]
// 8 warps: wid&3 -> o-slice (M16), wid>>2 -> b-half (N16 = 2 n-tiles).
// Patches: smem [32][580] tf32-prerounded, conflict-free fragment reads.
// Weights: streamed gmem -> cvt.rna.tf32 -> double-buffered smem [64][36].

#define B_    32
#define CI_   64
#define CO_   64
#define H_    32
#define W_    32
#define KTOT  576
#define KC    32
#define NCHUNK 18
#define NT    256
#define PS_W  580          // (4b+k)%32 distinct -> conflict-free B-fragment LDS
#define WSS   36           // (4o+k)%32 distinct -> conflict-free A-fragment LDS

#define PS_WORDS (B_ * PS_W)            // 18560
#define WS_WORDS (CO_ * WSS)            // 2304
#define SMEM_BYTES ((PS_WORDS + 2 * WS_WORDS) * 4)   // 92672 -> 2 CTAs/SM

static __device__ __forceinline__ uint32_t cvt_tf32(float f) {
    uint32_t r;
    asm("cvt.rna.tf32.f32 %0, %1;" : "=r"(r) : "f"(f));
    return r;
}

static __device__ __forceinline__ void mma_tf32(float* c,
                                                uint32_t a0, uint32_t a1,
                                                uint32_t a2, uint32_t a3,
                                                uint32_t b0, uint32_t b1) {
    asm volatile(
        "mma.sync.aligned.m16n8k8.row.col.f32.tf32.tf32.f32 "
        "{%0,%1,%2,%3}, {%4,%5,%6,%7}, {%8,%9}, {%0,%1,%2,%3};"
        : "+f"(c[0]), "+f"(c[1]), "+f"(c[2]), "+f"(c[3])
        : "r"(a0), "r"(a1), "r"(a2), "r"(a3), "r"(b0), "r"(b1));
}

__global__ __launch_bounds__(NT, 2)
void local2d_mma(const float* __restrict__ x,
                 const float* __restrict__ wgt,
                 const float* __restrict__ bias,
                 float* __restrict__ out)
{
    extern __shared__ uint32_t sm[];
    uint32_t* PS  = sm;                    // [32][PS_W] patch tf32 bits
    uint32_t* WS0 = sm + PS_WORDS;         // [64][WSS] weight chunk buf 0
    uint32_t* WS1 = WS0 + WS_WORDS;        // buf 1

    const int pos = blockIdx.x;
    const int x0  = pos >> 5;
    const int y0  = pos & 31;
    const int t   = threadIdx.x;
    const int lane = t & 31;
    const int wid  = t >> 5;
    const int owarp = wid & 3;             // o-slice (16 wide)
    const int bhalf = wid >> 2;            // b-half (16 wide)

    // ---- patch gather: x -> PS (tf32 pre-rounded), once ----
    for (int idx = t; idx < B_ * CI_ * 3; idx += NT) {
        int b   = idx / (CI_ * 3);
        int rem = idx - b * (CI_ * 3);
        int i   = rem / 3;
        int kh  = rem - i * 3;
        int h   = x0 + kh - 1;
        bool hok = ((unsigned)h < (unsigned)H_);
        const float* xrow = x + (((size_t)(b * CI_ + i) * H_ + h) * W_);
        int kbase = i * 9 + kh * 3;
        #pragma unroll
        for (int kw = 0; kw < 3; kw++) {
            int wc = y0 + kw - 1;
            float v = (hok && (unsigned)wc < (unsigned)W_) ? xrow[wc] : 0.0f;
            PS[b * PS_W + kbase + kw] = cvt_tf32(v);
        }
    }

    const float* wpos = wgt + (size_t)pos * CO_ * KTOT;   // W[o][k], k contiguous

    // weight staging mapping: thread handles 2 (o, k-quad) float4s per chunk
    const int o0  = t >> 3;            // q = t      -> o 0..31
    const int kq0 = t & 7;
    // second: q = t + 256 -> o 32..63, same kq

    // stage chunk 0 into WS0
    {
        const float* wp = wpos;
        #pragma unroll
        for (int j = 0; j < 2; j++) {
            int o = o0 + 32 * j;
            float4 v = *(const float4*)(wp + (size_t)o * KTOT + kq0 * 4);
            uint32_t* dst = WS0 + o * WSS + kq0 * 4;
            *(uint4*)dst = make_uint4(cvt_tf32(v.x), cvt_tf32(v.y),
                                      cvt_tf32(v.z), cvt_tf32(v.w));
        }
    }
    __syncthreads();

    // fragment base indices
    const int frow = lane >> 2;        // 0..7
    const int fk   = lane & 3;         // 0..3
    const int oA   = owarp * 16 + frow;
    const int bB   = bhalf * 16 + frow;

    float acc[2][4];
    #pragma unroll
    for (int nt = 0; nt < 2; nt++)
        #pragma unroll
        for (int r = 0; r < 4; r++)
            acc[nt][r] = 0.0f;

    for (int c = 0; c < NCHUNK; c++) {
        const uint32_t* Wb = (c & 1) ? WS1 : WS0;
        uint32_t* Wn = (c & 1) ? WS0 : WS1;

        // prefetch next chunk (gmem -> regs), overlaps compute
        float4 pf[2];
        if (c + 1 < NCHUNK) {
            const float* wp = wpos + (c + 1) * KC;
            #pragma unroll
            for (int j = 0; j < 2; j++)
                pf[j] = *(const float4*)(wp + (size_t)(o0 + 32 * j) * KTOT + kq0 * 4);
        }

        // compute: 4 K8-steps on this chunk
        #pragma unroll
        for (int ks = 0; ks < 4; ks++) {
            int kk = ks * 8 + fk;
            uint32_t a0 = Wb[oA * WSS + kk];
            uint32_t a1 = Wb[(oA + 8) * WSS + kk];
            uint32_t a2 = Wb[oA * WSS + kk + 4];
            uint32_t a3 = Wb[(oA + 8) * WSS + kk + 4];
            int kp = c * KC + ks * 8 + fk;
            uint32_t b0 = PS[bB * PS_W + kp];
            uint32_t b1 = PS[bB * PS_W + kp + 4];
            uint32_t b2 = PS[(bB + 8) * PS_W + kp];
            uint32_t b3 = PS[(bB + 8) * PS_W + kp + 4];
            mma_tf32(acc[0], a0, a1, a2, a3, b0, b1);
            mma_tf32(acc[1], a0, a1, a2, a3, b2, b3);
        }

        // store prefetched chunk to the other buffer
        if (c + 1 < NCHUNK) {
            #pragma unroll
            for (int j = 0; j < 2; j++) {
                int o = o0 + 32 * j;
                uint32_t* dst = Wn + o * WSS + kq0 * 4;
                *(uint4*)dst = make_uint4(cvt_tf32(pf[j].x), cvt_tf32(pf[j].y),
                                          cvt_tf32(pf[j].z), cvt_tf32(pf[j].w));
            }
        }
        __syncthreads();
    }

    // ---- epilogue: D rows = o, cols = b; add bias, scatter-store ----
    // c0:(r, 2c) c1:(r, 2c+1) c2:(r+8, 2c) c3:(r+8, 2c+1)
    const int ccol = (lane & 3) * 2;
    float bv0 = bias[(size_t)oA * (H_ * W_) + pos];
    float bv1 = bias[(size_t)(oA + 8) * (H_ * W_) + pos];

    #pragma unroll
    for (int nt = 0; nt < 2; nt++) {
        int bcol = bhalf * 16 + nt * 8 + ccol;
        #pragma unroll
        for (int r = 0; r < 4; r++) {
            int o = oA + ((r >= 2) ? 8 : 0);
            int b = bcol + (r & 1);
            float bv = (r >= 2) ? bv1 : bv0;
            out[((size_t)(b * CO_ + o)) * (H_ * W_) + pos] = acc[nt][r] + bv;
        }
    }
}

extern "C" void kernel_launch(void* const* d_in, const int* in_sizes, int n_in,
                              void* d_out, int out_size)
{
    const float* x    = (const float*)d_in[0];
    const float* wgt  = (const float*)d_in[1];
    const float* bias = (const float*)d_in[2];
    float* out        = (float*)d_out;

    cudaFuncSetAttribute(local2d_mma,
                         cudaFuncAttributeMaxDynamicSharedMemorySize, SMEM_BYTES);

    dim3 grid(H_ * W_);
    dim3 block(NT);
    local2d_mma<<<grid, block, SMEM_BYTES>>>(x, wgt, bias, out);
}

// round 8
// speedup vs baseline: 1.3283x; 1.0019x over previous
#include <cuda_runtime.h>
#include <cstdint>
#include <cstddef>

// Local2d via mma.sync tf32 (m16n8k8): per position GEMM
//   D[64o x 32b] = W[64o x 576k] * P[576k x 32b]
// 8 warps: wid&3 -> o-slice (M16), wid>>2 -> b-half (N16 = 2 n-tiles).
// k-interleaved smem layouts (group by k%4) so fragment loads are LDS.128:
//   weights WS[o][j], j=(k%4)*8 + k/4, row stride 36 words (double buffered)
//   patches PS[b][j], j=(k%4)*148 + k/4, row stride 592 words

#define B_    32
#define CI_   64
#define CO_   64
#define H_    32
#define W_    32
#define KTOT  576
#define KC    32
#define NCHUNK 18
#define NT    256
#define PS_R  592          // row stride words; group stride 148 -> conflict-free LDS.128
#define WS_R  36           // row stride words; conflict-free LDS.128

#define PS_WORDS (B_ * PS_R)            // 18944
#define WS_WORDS (CO_ * WS_R)           // 2304
#define SMEM_BYTES ((PS_WORDS + 2 * WS_WORDS) * 4)   // 94208 B -> 2 CTAs/SM

static __device__ __forceinline__ uint32_t cvt_tf32(float f) {
    uint32_t r;
    asm("cvt.rna.tf32.f32 %0, %1;" : "=r"(r) : "f"(f));
    return r;
}

static __device__ __forceinline__ void mma_tf32(float* c,
                                                uint32_t a0, uint32_t a1,
                                                uint32_t a2, uint32_t a3,
                                                uint32_t b0, uint32_t b1) {
    asm volatile(
        "mma.sync.aligned.m16n8k8.row.col.f32.tf32.tf32.f32 "
        "{%0,%1,%2,%3}, {%4,%5,%6,%7}, {%8,%9}, {%0,%1,%2,%3};"
        : "+f"(c[0]), "+f"(c[1]), "+f"(c[2]), "+f"(c[3])
        : "r"(a0), "r"(a1), "r"(a2), "r"(a3), "r"(b0), "r"(b1));
}

static __device__ __forceinline__ void lds128(uint32_t* r, const uint32_t* p) {
    uint4 v = *(const uint4*)p;
    r[0] = v.x; r[1] = v.y; r[2] = v.z; r[3] = v.w;
}

__global__ __launch_bounds__(NT, 2)
void local2d_mma(const float* __restrict__ x,
                 const float* __restrict__ wgt,
                 const float* __restrict__ bias,
                 float* __restrict__ out)
{
    extern __shared__ uint32_t sm[];
    uint32_t* PS  = sm;                    // [32][PS_R] patches, k-interleaved
    uint32_t* WS0 = sm + PS_WORDS;         // [64][WS_R] weight chunk buf 0
    uint32_t* WS1 = WS0 + WS_WORDS;        // buf 1

    const int pos = blockIdx.x;
    const int x0  = pos >> 5;
    const int y0  = pos & 31;
    const int t   = threadIdx.x;
    const int lane = t & 31;
    const int wid  = t >> 5;
    const int owarp = wid & 3;             // o-slice (16 wide)
    const int bhalf = wid >> 2;            // b-half (16 wide)

    // ---- patch gather: x -> PS (tf32 pre-rounded, k-interleaved), once ----
    for (int idx = t; idx < B_ * CI_ * 3; idx += NT) {
        int b   = idx / (CI_ * 3);
        int rem = idx - b * (CI_ * 3);
        int i   = rem / 3;
        int kh  = rem - i * 3;
        int h   = x0 + kh - 1;
        bool hok = ((unsigned)h < (unsigned)H_);
        const float* xrow = x + (((size_t)(b * CI_ + i) * H_ + h) * W_);
        int kbase = i * 9 + kh * 3;
        #pragma unroll
        for (int kw = 0; kw < 3; kw++) {
            int wc = y0 + kw - 1;
            float v = (hok && (unsigned)wc < (unsigned)W_) ? xrow[wc] : 0.0f;
            int k = kbase + kw;
            PS[b * PS_R + (k & 3) * 148 + (k >> 2)] = cvt_tf32(v);
        }
    }

    const float* wpos = wgt + (size_t)pos * CO_ * KTOT;   // W[o][k], k contiguous

    // weight staging: thread handles o = t>>3 and o+32, k-quad kq = t&7
    const int o0  = t >> 3;
    const int kq0 = t & 7;

    // stage chunk 0 into WS0 (k-interleaved: float4 elem m -> j = m*8 + kq)
    {
        #pragma unroll
        for (int j = 0; j < 2; j++) {
            int o = o0 + 32 * j;
            float4 v = *(const float4*)(wpos + (size_t)o * KTOT + kq0 * 4);
            uint32_t* dst = WS0 + o * WS_R + kq0;
            dst[0]  = cvt_tf32(v.x);
            dst[8]  = cvt_tf32(v.y);
            dst[16] = cvt_tf32(v.z);
            dst[24] = cvt_tf32(v.w);
        }
    }
    __syncthreads();

    // fragment base indices
    const int frow = lane >> 2;        // 0..7
    const int fk   = lane & 3;         // 0..3
    const int oA   = owarp * 16 + frow;
    const int bB   = bhalf * 16 + frow;

    const uint32_t* pB0 = PS + bB * PS_R + fk * 148;          // + c*8
    const uint32_t* pB1 = pB0 + 8 * PS_R;

    float acc[2][4];
    #pragma unroll
    for (int nt = 0; nt < 2; nt++)
        #pragma unroll
        for (int r = 0; r < 4; r++)
            acc[nt][r] = 0.0f;

    for (int c = 0; c < NCHUNK; c++) {
        const uint32_t* Wb = (c & 1) ? WS1 : WS0;
        uint32_t* Wn = (c & 1) ? WS0 : WS1;

        // prefetch next weight chunk (gmem -> regs), overlaps compute
        float4 pf[2];
        if (c + 1 < NCHUNK) {
            const float* wp = wpos + (c + 1) * KC;
            #pragma unroll
            for (int j = 0; j < 2; j++)
                pf[j] = *(const float4*)(wp + (size_t)(o0 + 32 * j) * KTOT + kq0 * 4);
        }

        // fragment loads: 8 x LDS.128 per warp per chunk
        uint32_t A0[8], A1[8], Bf0[8], Bf1[8];
        const uint32_t* wa0 = Wb + oA * WS_R + fk * 8;
        const uint32_t* wa1 = wa0 + 8 * WS_R;
        lds128(A0,     wa0);
        lds128(A0 + 4, wa0 + 4);
        lds128(A1,     wa1);
        lds128(A1 + 4, wa1 + 4);
        lds128(Bf0,     pB0 + c * 8);
        lds128(Bf0 + 4, pB0 + c * 8 + 4);
        lds128(Bf1,     pB1 + c * 8);
        lds128(Bf1 + 4, pB1 + c * 8 + 4);

        // 4 K8-steps: regs A0[2s]=a0, A1[2s]=a1, A0[2s+1]=a2, A1[2s+1]=a3
        #pragma unroll
        for (int s = 0; s < 4; s++) {
            mma_tf32(acc[0], A0[2*s], A1[2*s], A0[2*s+1], A1[2*s+1],
                     Bf0[2*s], Bf0[2*s+1]);
            mma_tf32(acc[1], A0[2*s], A1[2*s], A0[2*s+1], A1[2*s+1],
                     Bf1[2*s], Bf1[2*s+1]);
        }

        // store prefetched chunk (k-interleaved) to the other buffer
        if (c + 1 < NCHUNK) {
            #pragma unroll
            for (int j = 0; j < 2; j++) {
                int o = o0 + 32 * j;
                uint32_t* dst = Wn + o * WS_R + kq0;
                dst[0]  = cvt_tf32(pf[j].x);
                dst[8]  = cvt_tf32(pf[j].y);
                dst[16] = cvt_tf32(pf[j].z);
                dst[24] = cvt_tf32(pf[j].w);
            }
        }
        __syncthreads();
    }

    // ---- epilogue: D rows = o, cols = b; add bias, scatter-store ----
    const int ccol = (lane & 3) * 2;
    float bv0 = bias[(size_t)oA * (H_ * W_) + pos];
    float bv1 = bias[(size_t)(oA + 8) * (H_ * W_) + pos];

    #pragma unroll
    for (int nt = 0; nt < 2; nt++) {
        int bcol = bhalf * 16 + nt * 8 + ccol;
        #pragma unroll
        for (int r = 0; r < 4; r++) {
            int o = oA + ((r >= 2) ? 8 : 0);
            int b = bcol + (r & 1);
            float bv = (r >= 2) ? bv1 : bv0;
            out[((size_t)(b * CO_ + o)) * (H_ * W_) + pos] = acc[nt][r] + bv;
        }
    }
}

extern "C" void kernel_launch(void* const* d_in, const int* in_sizes, int n_in,
                              void* d_out, int out_size)
{
    const float* x    = (const float*)d_in[0];
    const float* wgt  = (const float*)d_in[1];
    const float* bias = (const float*)d_in[2];
    float* out        = (float*)d_out;

    cudaFuncSetAttribute(local2d_mma,
                         cudaFuncAttributeMaxDynamicSharedMemorySize, SMEM_BYTES);

    dim3 grid(H_ * W_);
    dim3 block(NT);
    local2d_mma<<<grid, block, SMEM_BYTES>>>(x, wgt, bias, out);
}

// round 10
// speedup vs baseline: 2.3782x; 1.7903x over previous
#include <cuda_runtime.h>
#include <cstdint>
#include <cstddef>

// Local2d via mma.sync tf32, restructured for coalescing:
//  K0: zero XT
//  K1: transpose x[b][i][h][w] -> XT[i][h+1][w+1][b] (tf32 bits, zero borders)
//  K2: per-position GEMM D[64o x 32b] = W * P; patches gathered as whole
//      128B lines from XT; D (+bias) stored contiguously to DT[pos][b*64+o]
//  K3: transpose DT[pos][bo] -> out[bo][pos]

#define B_    32
#define CI_   64
#define CO_   64
#define H_    32
#define W_    32
#define KTOT  576
#define KC    32
#define NCHUNK 18
#define NT    256
#define PS_R  40            // PS row stride (words): frag banks (8fk+frow) distinct
#define WS_R  36

#define XT_WORDS (CI_ * 34 * 34 * B_)     // 2,367,488
#define DT_WORDS (1024 * B_ * CO_)        // 2,097,152

__device__ uint32_t XTg[XT_WORDS];
__device__ float    DTg[DT_WORDS];

#define PS_WORDS (KTOT * PS_R)            // 23040
#define WS_WORDS (CO_ * WS_R)             // 2304
#define SMEM_BYTES ((PS_WORDS + 2 * WS_WORDS) * 4)   // 110592 -> 2 CTAs/SM

static __device__ __forceinline__ uint32_t cvt_tf32(float f) {
    uint32_t r;
    asm("cvt.rna.tf32.f32 %0, %1;" : "=r"(r) : "f"(f));
    return r;
}

static __device__ __forceinline__ void mma_tf32(float* c,
                                                uint32_t a0, uint32_t a1,
                                                uint32_t a2, uint32_t a3,
                                                uint32_t b0, uint32_t b1) {
    asm volatile(
        "mma.sync.aligned.m16n8k8.row.col.f32.tf32.tf32.f32 "
        "{%0,%1,%2,%3}, {%4,%5,%6,%7}, {%8,%9}, {%0,%1,%2,%3};"
        : "+f"(c[0]), "+f"(c[1]), "+f"(c[2]), "+f"(c[3])
        : "r"(a0), "r"(a1), "r"(a2), "r"(a3), "r"(b0), "r"(b1));
}

// ---- K0: zero XT ----
__global__ void k_zero() {
    int idx = blockIdx.x * blockDim.x + threadIdx.x;     // uint4 index
    if (idx < XT_WORDS / 4)
        ((uint4*)XTg)[idx] = make_uint4(0u, 0u, 0u, 0u);
}

// ---- K1: x -> XT (transpose b<->w, tf32 convert, +1 borders) ----
__global__ __launch_bounds__(256)
void k_tin(const float* __restrict__ x) {
    __shared__ uint32_t tile[32][33];
    const int i = blockIdx.x;        // 0..63
    const int h = blockIdx.y;        // 0..31
    const int tx = threadIdx.x;      // 0..31
    const int ty = threadIdx.y;      // 0..7
    #pragma unroll
    for (int r = 0; r < 4; r++) {
        int b = ty + 8 * r;
        tile[b][tx] = cvt_tf32(x[(((size_t)(b * CI_ + i) * H_ + h) * W_) + tx]);
    }
    __syncthreads();
    #pragma unroll
    for (int r = 0; r < 4; r++) {
        int w = ty + 8 * r;
        XTg[((size_t)(i * 34 + h + 1) * 34 + (w + 1)) * B_ + tx] = tile[tx][w];
    }
}

// ---- K2: main GEMM ----
__global__ __launch_bounds__(NT, 2)
void local2d_mma(const float* __restrict__ wgt,
                 const float* __restrict__ bias)
{
    extern __shared__ uint32_t sm[];
    uint32_t* PS  = sm;                    // [KTOT][PS_R] patches, b contiguous
    uint32_t* WS0 = sm + PS_WORDS;         // [64][WS_R] weight chunk (k-interleaved)
    uint32_t* WS1 = WS0 + WS_WORDS;

    const int pos = blockIdx.x;
    const int x0  = pos >> 5;
    const int y0  = pos & 31;
    const int t   = threadIdx.x;
    const int lane = t & 31;
    const int wid  = t >> 5;
    const int owarp = wid & 3;
    const int bhalf = wid >> 2;

    // ---- patch gather: 576 lines of 128B from XT, fully coalesced ----
    #pragma unroll
    for (int j = 0; j < 18; j++) {
        int idx = t + NT * j;              // 0..4607 (uint4 units)
        int k   = idx >> 3;
        int q   = idx & 7;
        int i   = k / 9;
        int r9  = k - i * 9;
        int kh  = r9 / 3;
        int kw  = r9 - kh * 3;
        const uint4 v = *(const uint4*)(XTg +
            ((size_t)((i * 34 + x0 + kh) * 34 + (y0 + kw)) << 5) + (q << 2));
        *(uint4*)(PS + k * PS_R + (q << 2)) = v;
    }

    const float* wpos = wgt + (size_t)pos * CO_ * KTOT;

    const int o0  = t >> 3;
    const int kq0 = t & 7;

    // stage chunk 0 into WS0
    #pragma unroll
    for (int j = 0; j < 2; j++) {
        int o = o0 + 32 * j;
        float4 v = *(const float4*)(wpos + (size_t)o * KTOT + kq0 * 4);
        uint32_t* dst = WS0 + o * WS_R + kq0;
        dst[0]  = cvt_tf32(v.x);
        dst[8]  = cvt_tf32(v.y);
        dst[16] = cvt_tf32(v.z);
        dst[24] = cvt_tf32(v.w);
    }
    __syncthreads();

    const int frow = lane >> 2;
    const int fk   = lane & 3;
    const int oA   = owarp * 16 + frow;
    const int bB   = bhalf * 16 + frow;

    const uint32_t* pB = PS + fk * PS_R + bB;    // + kstep*8*PS_R + c*KC*PS_R

    float acc[2][4];
    #pragma unroll
    for (int nt = 0; nt < 2; nt++)
        #pragma unroll
        for (int r = 0; r < 4; r++)
            acc[nt][r] = 0.0f;

    for (int c = 0; c < NCHUNK; c++) {
        const uint32_t* Wb = (c & 1) ? WS1 : WS0;
        uint32_t* Wn = (c & 1) ? WS0 : WS1;

        float4 pf[2];
        if (c + 1 < NCHUNK) {
            const float* wp = wpos + (c + 1) * KC;
            #pragma unroll
            for (int j = 0; j < 2; j++)
                pf[j] = *(const float4*)(wp + (size_t)(o0 + 32 * j) * KTOT + kq0 * 4);
        }

        // A fragments: 4 x LDS.128
        uint32_t A0[8], A1[8];
        {
            const uint32_t* wa0 = Wb + oA * WS_R + fk * 8;
            const uint32_t* wa1 = wa0 + 8 * WS_R;
            uint4 u0 = *(const uint4*)wa0;
            uint4 u1 = *(const uint4*)(wa0 + 4);
            uint4 u2 = *(const uint4*)wa1;
            uint4 u3 = *(const uint4*)(wa1 + 4);
            A0[0]=u0.x; A0[1]=u0.y; A0[2]=u0.z; A0[3]=u0.w;
            A0[4]=u1.x; A0[5]=u1.y; A0[6]=u1.z; A0[7]=u1.w;
            A1[0]=u2.x; A1[1]=u2.y; A1[2]=u2.z; A1[3]=u2.w;
            A1[4]=u3.x; A1[5]=u3.y; A1[6]=u3.z; A1[7]=u3.w;
        }

        const uint32_t* pc = pB + c * KC * PS_R;
        #pragma unroll
        for (int s = 0; s < 4; s++) {
            const uint32_t* pk = pc + s * 8 * PS_R;
            uint32_t b0 = pk[0];
            uint32_t b1 = pk[4 * PS_R];
            uint32_t b2 = pk[8];
            uint32_t b3 = pk[4 * PS_R + 8];
            mma_tf32(acc[0], A0[2*s], A1[2*s], A0[2*s+1], A1[2*s+1], b0, b1);
            mma_tf32(acc[1], A0[2*s], A1[2*s], A0[2*s+1], A1[2*s+1], b2, b3);
        }

        if (c + 1 < NCHUNK) {
            #pragma unroll
            for (int j = 0; j < 2; j++) {
                int o = o0 + 32 * j;
                uint32_t* dst = Wn + o * WS_R + kq0;
                dst[0]  = cvt_tf32(pf[j].x);
                dst[8]  = cvt_tf32(pf[j].y);
                dst[16] = cvt_tf32(pf[j].z);
                dst[24] = cvt_tf32(pf[j].w);
            }
        }
        __syncthreads();
    }

    // ---- epilogue: bias + contiguous store to DT[pos][b*64+o] ----
    const int ccol = (lane & 3) * 2;
    float bv0 = bias[(size_t)oA * (H_ * W_) + pos];
    float bv1 = bias[(size_t)(oA + 8) * (H_ * W_) + pos];
    float* dt = DTg + (size_t)pos * (B_ * CO_);

    #pragma unroll
    for (int nt = 0; nt < 2; nt++) {
        int bcol = bhalf * 16 + nt * 8 + ccol;
        #pragma unroll
        for (int r = 0; r < 4; r++) {
            int o = oA + ((r >= 2) ? 8 : 0);
            int b = bcol + (r & 1);
            float bv = (r >= 2) ? bv1 : bv0;
            dt[b * CO_ + o] = acc[nt][r] + bv;
        }
    }
}

// ---- K3: DT[pos][bo] -> out[bo][pos] ----
__global__ __launch_bounds__(256)
void k_tout(float* __restrict__ out) {
    __shared__ float tile[32][33];
    const int pos0 = blockIdx.x * 32;
    const int bo0  = blockIdx.y * 32;
    const int tx = threadIdx.x;
    const int ty = threadIdx.y;
    #pragma unroll
    for (int r = 0; r < 4; r++) {
        int p = ty + 8 * r;
        tile[p][tx] = DTg[(size_t)(pos0 + p) * (B_ * CO_) + bo0 + tx];
    }
    __syncthreads();
    #pragma unroll
    for (int r = 0; r < 4; r++) {
        int bo = ty + 8 * r;
        out[(size_t)(bo0 + bo) * 1024 + pos0 + tx] = tile[tx][bo];
    }
}

extern "C" void kernel_launch(void* const* d_in, const int* in_sizes, int n_in,
                              void* d_out, int out_size)
{
    const float* x    = (const float*)d_in[0];
    const float* wgt  = (const float*)d_in[1];
    const float* bias = (const float*)d_in[2];
    float* out        = (float*)d_out;

    cudaFuncSetAttribute(local2d_mma,
                         cudaFuncAttributeMaxDynamicSharedMemorySize, SMEM_BYTES);

    k_zero<<<(XT_WORDS / 4 + 255) / 256, 256>>>();
    k_tin<<<dim3(CI_, H_), dim3(32, 8)>>>(x);
    local2d_mma<<<1024, NT, SMEM_BYTES>>>(wgt, bias);
    k_tout<<<dim3(32, 64), dim3(32, 8)>>>(out);
}

// round 11
// speedup vs baseline: 3.1491x; 1.3242x over previous
#include <cuda_runtime.h>
#include <cstdint>
#include <cstddef>

// Local2d via mma.sync tf32, K-split + cp.async weight pipeline:
//  K0: zero XT
//  K1: transpose x[b][i][h][w] -> XT[i][h+1][w+1][b] (tf32 bits, zero borders)
//  K2: grid (1024 pos, 2 ksplit). Per CTA: D_part[64o x 32b] over 288 k.
//      Patches: 288 coalesced 128B lines from XT -> PS[288][40].
//      Weights: 6-stage cp.async ring, raw fp32 [64][36], cvt.rna at frag load.
//      Partial D stored contiguously to DT[ks][pos][b*64+o].
//  K3: out[bo][pos] = DT[0][pos][bo] + DT[1][pos][bo] + bias[bo%64][pos]

#define B_    32
#define CI_   64
#define CO_   64
#define H_    32
#define W_    32
#define KTOT  576
#define KSP   288
#define KC    32
#define NC    9
#define NSTAGE 6
#define NT    256
#define PS_R  40
#define WS_R  36

#define XT_WORDS (CI_ * 34 * 34 * B_)     // 2,367,488
#define DT_HALF  (1024 * B_ * CO_)        // 2,097,152
__device__ uint32_t XTg[XT_WORDS];
__device__ float    DTg[2 * DT_HALF];

#define PS_WORDS (KSP * PS_R)             // 11520
#define WS_WORDS (CO_ * WS_R)             // 2304
#define SMEM_BYTES ((PS_WORDS + NSTAGE * WS_WORDS) * 4)   // 101376 -> 2 CTAs/SM

static __device__ __forceinline__ uint32_t cvt_tf32(float f) {
    uint32_t r;
    asm("cvt.rna.tf32.f32 %0, %1;" : "=r"(r) : "f"(f));
    return r;
}

static __device__ __forceinline__ void mma_tf32(float* c,
                                                uint32_t a0, uint32_t a1,
                                                uint32_t a2, uint32_t a3,
                                                uint32_t b0, uint32_t b1) {
    asm volatile(
        "mma.sync.aligned.m16n8k8.row.col.f32.tf32.tf32.f32 "
        "{%0,%1,%2,%3}, {%4,%5,%6,%7}, {%8,%9}, {%0,%1,%2,%3};"
        : "+f"(c[0]), "+f"(c[1]), "+f"(c[2]), "+f"(c[3])
        : "r"(a0), "r"(a1), "r"(a2), "r"(a3), "r"(b0), "r"(b1));
}

static __device__ __forceinline__ void cpasync16(uint32_t dst, const float* src) {
    asm volatile("cp.async.cg.shared.global [%0], [%1], 16;"
                 :: "r"(dst), "l"(src) : "memory");
}

// ---- K0: zero XT ----
__global__ void k_zero() {
    int idx = blockIdx.x * blockDim.x + threadIdx.x;
    if (idx < XT_WORDS / 4)
        ((uint4*)XTg)[idx] = make_uint4(0u, 0u, 0u, 0u);
}

// ---- K1: x -> XT (transpose b<->w, tf32 convert, +1 borders) ----
__global__ __launch_bounds__(256)
void k_tin(const float* __restrict__ x) {
    __shared__ uint32_t tile[32][33];
    const int i = blockIdx.x;
    const int h = blockIdx.y;
    const int tx = threadIdx.x;
    const int ty = threadIdx.y;
    #pragma unroll
    for (int r = 0; r < 4; r++) {
        int b = ty + 8 * r;
        tile[b][tx] = cvt_tf32(x[(((size_t)(b * CI_ + i) * H_ + h) * W_) + tx]);
    }
    __syncthreads();
    #pragma unroll
    for (int r = 0; r < 4; r++) {
        int w = ty + 8 * r;
        XTg[((size_t)(i * 34 + h + 1) * 34 + (w + 1)) * B_ + tx] = tile[tx][w];
    }
}

// ---- K2: main GEMM (K-split halves) ----
__global__ __launch_bounds__(NT, 2)
void local2d_mma(const float* __restrict__ wgt)
{
    extern __shared__ uint32_t sm[];
    uint32_t* PS = sm;                       // [KSP][PS_R]
    uint32_t* WS = sm + PS_WORDS;            // NSTAGE x [64][WS_R] raw fp32 ring

    uint32_t smU32;
    asm("{ .reg .u64 tt; cvta.to.shared.u64 tt, %1; cvt.u32.u64 %0, tt; }"
        : "=r"(smU32) : "l"(sm));
    const uint32_t wsU32 = smU32 + PS_WORDS * 4;

    const int pos = blockIdx.x;
    const int ks  = blockIdx.y;              // 0/1 k-split
    const int x0  = pos >> 5;
    const int y0  = pos & 31;
    const int t   = threadIdx.x;
    const int lane = t & 31;
    const int wid  = t >> 5;
    const int owarp = wid & 3;
    const int bhalf = wid >> 2;

    const float* wpos = wgt + (size_t)pos * CO_ * KTOT + ks * KSP;
    const int o0  = t >> 3;                  // cp.async mapping: o0, o0+32
    const int kq0 = t & 7;

    // ---- prologue: issue weight chunks 0..4 into stages 0..4 ----
    #pragma unroll
    for (int s = 0; s < NSTAGE - 1; s++) {
        #pragma unroll
        for (int j = 0; j < 2; j++) {
            int o = o0 + 32 * j;
            cpasync16(wsU32 + (uint32_t)(s * WS_WORDS + o * WS_R + kq0 * 4) * 4,
                      wpos + (size_t)o * KTOT + s * KC + kq0 * 4);
        }
        asm volatile("cp.async.commit_group;" ::: "memory");
    }

    // ---- patch gather: 288 coalesced 128B lines from XT -> PS ----
    const int ib = ks * 32;
    #pragma unroll
    for (int j = 0; j < 9; j++) {
        int idx = t + NT * j;                // 0..2303 (uint4 units)
        int kl  = idx >> 3;
        int q   = idx & 7;
        int il  = kl / 9;
        int r9  = kl - il * 9;
        int kh  = r9 / 3;
        int kw  = r9 - kh * 3;
        const uint4 v = *(const uint4*)(XTg +
            ((size_t)(((ib + il) * 34 + x0 + kh) * 34 + (y0 + kw)) << 5) + (q << 2));
        *(uint4*)(PS + kl * PS_R + (q << 2)) = v;
    }

    __syncthreads();                          // PS ready for all warps

    const int frow = lane >> 2;
    const int fk   = lane & 3;
    const int oA   = owarp * 16 + frow;
    const int bB   = bhalf * 16 + frow;

    float acc[2][4];
    #pragma unroll
    for (int nt = 0; nt < 2; nt++)
        #pragma unroll
        for (int r = 0; r < 4; r++)
            acc[nt][r] = 0.0f;

    for (int c = 0; c < NC; c++) {
        // wait for chunk c's group (<=4 younger pending), then make visible
        asm volatile("cp.async.wait_group 4;" ::: "memory");
        __syncthreads();

        // issue chunk c+5 into stage (c+5)%6 (safe: all warps are past chunk c-1)
        if (c + NSTAGE - 1 < NC) {
            int cc = c + NSTAGE - 1;
            int st = cc % NSTAGE;
            #pragma unroll
            for (int j = 0; j < 2; j++) {
                int o = o0 + 32 * j;
                cpasync16(wsU32 + (uint32_t)(st * WS_WORDS + o * WS_R + kq0 * 4) * 4,
                          wpos + (size_t)o * KTOT + cc * KC + kq0 * 4);
            }
        }
        asm volatile("cp.async.commit_group;" ::: "memory");

        // compute chunk c from stage c%6
        const float* Wf = (const float*)(WS + (c % NSTAGE) * WS_WORDS);
        const uint32_t* pc = PS + (c * KC) * PS_R + bB;

        #pragma unroll
        for (int s = 0; s < 4; s++) {
            int kb = 8 * s + fk;
            uint32_t a0 = cvt_tf32(Wf[oA * WS_R + kb]);
            uint32_t a1 = cvt_tf32(Wf[(oA + 8) * WS_R + kb]);
            uint32_t a2 = cvt_tf32(Wf[oA * WS_R + kb + 4]);
            uint32_t a3 = cvt_tf32(Wf[(oA + 8) * WS_R + kb + 4]);
            const uint32_t* pk = pc + kb * PS_R;
            uint32_t b0 = pk[0];
            uint32_t b1 = pk[4 * PS_R];
            uint32_t b2 = pk[8];
            uint32_t b3 = pk[4 * PS_R + 8];
            mma_tf32(acc[0], a0, a1, a2, a3, b0, b1);
            mma_tf32(acc[1], a0, a1, a2, a3, b2, b3);
        }
    }

    // ---- epilogue: contiguous partial store to DT[ks][pos][b*64+o] ----
    const int ccol = (lane & 3) * 2;
    float* dt = DTg + (size_t)ks * DT_HALF + (size_t)pos * (B_ * CO_);

    #pragma unroll
    for (int nt = 0; nt < 2; nt++) {
        int bcol = bhalf * 16 + nt * 8 + ccol;
        #pragma unroll
        for (int r = 0; r < 4; r++) {
            int o = oA + ((r >= 2) ? 8 : 0);
            int b = bcol + (r & 1);
            dt[b * CO_ + o] = acc[nt][r];
        }
    }
}

// ---- K3: out[bo][pos] = DT0 + DT1 + bias ----
__global__ __launch_bounds__(256)
void k_tout(float* __restrict__ out, const float* __restrict__ bias) {
    __shared__ float tile[32][33];
    const int pos0 = blockIdx.x * 32;
    const int bo0  = blockIdx.y * 32;
    const int tx = threadIdx.x;
    const int ty = threadIdx.y;
    #pragma unroll
    for (int r = 0; r < 4; r++) {
        int p = ty + 8 * r;
        size_t idx = (size_t)(pos0 + p) * (B_ * CO_) + bo0 + tx;
        tile[p][tx] = DTg[idx] + DTg[DT_HALF + idx];
    }
    __syncthreads();
    #pragma unroll
    for (int r = 0; r < 4; r++) {
        int bo = bo0 + ty + 8 * r;
        float bv = bias[(size_t)(bo & 63) * 1024 + pos0 + tx];
        out[(size_t)bo * 1024 + pos0 + tx] = tile[tx][ty + 8 * r] + bv;
    }
}

extern "C" void kernel_launch(void* const* d_in, const int* in_sizes, int n_in,
                              void* d_out, int out_size)
{
    const float* x    = (const float*)d_in[0];
    const float* wgt  = (const float*)d_in[1];
    const float* bias = (const float*)d_in[2];
    float* out        = (float*)d_out;

    cudaFuncSetAttribute(local2d_mma,
                         cudaFuncAttributeMaxDynamicSharedMemorySize, SMEM_BYTES);

    k_zero<<<(XT_WORDS / 4 + 255) / 256, 256>>>();
    k_tin<<<dim3(CI_, H_), dim3(32, 8)>>>(x);
    local2d_mma<<<dim3(1024, 2), NT, SMEM_BYTES>>>(wgt);
    k_tout<<<dim3(32, 64), dim3(32, 8)>>>(out, bias);
}

// round 12
// speedup vs baseline: 3.2769x; 1.0406x over previous
#include <cuda_runtime.h>
#include <cstdint>
#include <cstddef>

// Local2d via mma.sync tf32; warp-local cp.async weight pipeline:
//  K0: zero XT borders only
//  K1: transpose x[b][i][h][w] -> XT[i][h+1][w+1][b] (tf32 bits)
//  K2: grid (1024 pos, 2 ksplit), 4 warps/CTA. Warp w owns weight rows
//      [w*16, w*16+16) and computes D_part[16o x 32b] over 288 k.
//      Per-warp 7-stage cp.async ring, wait_group/syncwarp only (no block sync
//      in mainloop). Partials -> DT[ks][pos][b*64+o].
//  K3: out[bo][pos] = DT[0][pos][bo] + DT[1][pos][bo] + bias[bo%64][pos]

#define B_    32
#define CI_   64
#define CO_   64
#define H_    32
#define W_    32
#define KTOT  576
#define KSP   288
#define KC    32
#define NC    9
#define NSTAGE 7
#define NT    128
#define PS_R  40
#define WS_R  36

#define XT_WORDS (CI_ * 34 * 34 * B_)
#define DT_HALF  (1024 * B_ * CO_)
__device__ uint32_t XTg[XT_WORDS];
__device__ float    DTg[2 * DT_HALF];

#define PS_WORDS (KSP * PS_R)                 // 11520
#define WS_WORDS (CO_ * WS_R)                 // 2304
#define SMEM_BYTES ((PS_WORDS + NSTAGE * WS_WORDS) * 4)   // 110592 -> 2 CTAs/SM

static __device__ __forceinline__ uint32_t cvt_tf32(float f) {
    uint32_t r;
    asm("cvt.rna.tf32.f32 %0, %1;" : "=r"(r) : "f"(f));
    return r;
}

static __device__ __forceinline__ void mma_tf32(float* c,
                                                uint32_t a0, uint32_t a1,
                                                uint32_t a2, uint32_t a3,
                                                uint32_t b0, uint32_t b1) {
    asm volatile(
        "mma.sync.aligned.m16n8k8.row.col.f32.tf32.tf32.f32 "
        "{%0,%1,%2,%3}, {%4,%5,%6,%7}, {%8,%9}, {%0,%1,%2,%3};"
        : "+f"(c[0]), "+f"(c[1]), "+f"(c[2]), "+f"(c[3])
        : "r"(a0), "r"(a1), "r"(a2), "r"(a3), "r"(b0), "r"(b1));
}

static __device__ __forceinline__ void cpasync16(uint32_t dst, const float* src) {
    asm volatile("cp.async.cg.shared.global [%0], [%1], 16;"
                 :: "r"(dst), "l"(src) : "memory");
}

// ---- K0: zero XT border cells only ----
// cells per i: h=0 (34), h=33 (34), w=0 h=1..32 (32), w=33 h=1..32 (32) = 132
__global__ void k_zero() {
    int idx = blockIdx.x * blockDim.x + threadIdx.x;   // (i,cell,quad): 64*132*8
    if (idx >= 64 * 132 * 8) return;
    int q    = idx & 7;
    int cell = (idx >> 3) % 132;
    int i    = (idx >> 3) / 132;
    int h, w;
    if (cell < 34)       { h = 0;  w = cell; }
    else if (cell < 68)  { h = 33; w = cell - 34; }
    else if (cell < 100) { h = cell - 68 + 1; w = 0; }
    else                 { h = cell - 100 + 1; w = 33; }
    uint4* p = (uint4*)(XTg + ((size_t)(i * 34 + h) * 34 + w) * B_);
    p[q] = make_uint4(0u, 0u, 0u, 0u);
}

// ---- K1: x -> XT (transpose b<->w, tf32 convert, +1 borders) ----
__global__ __launch_bounds__(256)
void k_tin(const float* __restrict__ x) {
    __shared__ uint32_t tile[32][33];
    const int i = blockIdx.x;
    const int h = blockIdx.y;
    const int tx = threadIdx.x;
    const int ty = threadIdx.y;
    #pragma unroll
    for (int r = 0; r < 4; r++) {
        int b = ty + 8 * r;
        tile[b][tx] = cvt_tf32(x[(((size_t)(b * CI_ + i) * H_ + h) * W_) + tx]);
    }
    __syncthreads();
    #pragma unroll
    for (int r = 0; r < 4; r++) {
        int w = ty + 8 * r;
        XTg[((size_t)(i * 34 + h + 1) * 34 + (w + 1)) * B_ + tx] = tile[tx][w];
    }
}

// ---- K2: main GEMM, warp-local pipeline ----
__global__ __launch_bounds__(NT, 2)
void local2d_mma(const float* __restrict__ wgt)
{
    extern __shared__ uint32_t sm[];
    uint32_t* PS = sm;                       // [KSP][PS_R]
    uint32_t* WS = sm + PS_WORDS;            // NSTAGE x [64][WS_R] raw fp32 ring

    uint32_t smU32;
    asm("{ .reg .u64 tt; cvta.to.shared.u64 tt, %1; cvt.u32.u64 %0, tt; }"
        : "=r"(smU32) : "l"(sm));
    const uint32_t wsU32 = smU32 + PS_WORDS * 4;

    const int pos = blockIdx.x;
    const int ks  = blockIdx.y;
    const int x0  = pos >> 5;
    const int y0  = pos & 31;
    const int t   = threadIdx.x;
    const int lane = t & 31;
    const int wid  = t >> 5;                 // 0..3 = o-slice owner

    const float* wpos = wgt + (size_t)pos * CO_ * KTOT + ks * KSP
                      + (size_t)wid * 16 * KTOT;     // this warp's 16 rows

    // per-warp cp.async mapping: 4 x (row 0..15, quad 0..7)
    const int rw0 = lane >> 3;               // rows rw0, rw0+4, rw0+8, rw0+12
    const int qq  = lane & 7;

    // ---- prologue: issue chunks 0..5 into stages 0..5 (warp-local groups) ----
    #pragma unroll
    for (int s = 0; s < NSTAGE - 1; s++) {
        #pragma unroll
        for (int j = 0; j < 4; j++) {
            int row = rw0 + 4 * j;
            cpasync16(wsU32 + (uint32_t)(s * WS_WORDS + (wid * 16 + row) * WS_R + qq * 4) * 4,
                      wpos + (size_t)row * KTOT + s * KC + qq * 4);
        }
        asm volatile("cp.async.commit_group;" ::: "memory");
    }

    // ---- patch gather: 288 coalesced 128B lines from XT -> PS ----
    const int ib = ks * 32;
    #pragma unroll
    for (int j = 0; j < 18; j++) {
        int idx = t + NT * j;                // 0..2303 (uint4 units)
        int kl  = idx >> 3;
        int q   = idx & 7;
        int il  = kl / 9;
        int r9  = kl - il * 9;
        int kh  = r9 / 3;
        int kw  = r9 - kh * 3;
        const uint4 v = *(const uint4*)(XTg +
            ((size_t)(((ib + il) * 34 + x0 + kh) * 34 + (y0 + kw)) << 5) + (q << 2));
        *(uint4*)(PS + kl * PS_R + (q << 2)) = v;
    }
    __syncthreads();                          // PS visible to all warps (only block sync)

    const int frow = lane >> 2;
    const int fk   = lane & 3;
    const int oRow = wid * 16 + frow;         // A row (global o) for a0/a2

    float acc[4][4];
    #pragma unroll
    for (int nt = 0; nt < 4; nt++)
        #pragma unroll
        for (int r = 0; r < 4; r++)
            acc[nt][r] = 0.0f;

    for (int c = 0; c < NC; c++) {
        asm volatile("cp.async.wait_group 5;" ::: "memory");
        __syncwarp();

        // issue chunk c+6 into stage (c+6)%7 (warp-local; buffer last used at c-1)
        if (c + NSTAGE - 1 < NC) {
            int cc = c + NSTAGE - 1;
            int st = cc % NSTAGE;
            #pragma unroll
            for (int j = 0; j < 4; j++) {
                int row = rw0 + 4 * j;
                cpasync16(wsU32 + (uint32_t)(st * WS_WORDS + (wid * 16 + row) * WS_R + qq * 4) * 4,
                          wpos + (size_t)row * KTOT + cc * KC + qq * 4);
            }
        }
        asm volatile("cp.async.commit_group;" ::: "memory");

        const float* Wf = (const float*)(WS + (c % NSTAGE) * WS_WORDS);
        const uint32_t* pc = PS + (c * KC) * PS_R + frow;

        #pragma unroll
        for (int s = 0; s < 4; s++) {
            int kb = 8 * s + fk;
            uint32_t a0 = cvt_tf32(Wf[oRow * WS_R + kb]);
            uint32_t a1 = cvt_tf32(Wf[(oRow + 8) * WS_R + kb]);
            uint32_t a2 = cvt_tf32(Wf[oRow * WS_R + kb + 4]);
            uint32_t a3 = cvt_tf32(Wf[(oRow + 8) * WS_R + kb + 4]);
            const uint32_t* pk = pc + kb * PS_R;
            #pragma unroll
            for (int nt = 0; nt < 4; nt++) {
                uint32_t b0 = pk[8 * nt];
                uint32_t b1 = pk[4 * PS_R + 8 * nt];
                mma_tf32(acc[nt], a0, a1, a2, a3, b0, b1);
            }
        }
    }

    // ---- epilogue: partial store to DT[ks][pos][b*64+o] ----
    const int ccol = (lane & 3) * 2;
    float* dt = DTg + (size_t)ks * DT_HALF + (size_t)pos * (B_ * CO_);

    #pragma unroll
    for (int nt = 0; nt < 4; nt++) {
        int bcol = nt * 8 + ccol;
        #pragma unroll
        for (int r = 0; r < 4; r++) {
            int o = oRow + ((r >= 2) ? 8 : 0);
            int b = bcol + (r & 1);
            dt[b * CO_ + o] = acc[nt][r];
        }
    }
}

// ---- K3: out[bo][pos] = DT0 + DT1 + bias ----
__global__ __launch_bounds__(256)
void k_tout(float* __restrict__ out, const float* __restrict__ bias) {
    __shared__ float tile[32][33];
    const int pos0 = blockIdx.x * 32;
    const int bo0  = blockIdx.y * 32;
    const int tx = threadIdx.x;
    const int ty = threadIdx.y;
    #pragma unroll
    for (int r = 0; r < 4; r++) {
        int p = ty + 8 * r;
        size_t idx = (size_t)(pos0 + p) * (B_ * CO_) + bo0 + tx;
        tile[p][tx] = DTg[idx] + DTg[DT_HALF + idx];
    }
    __syncthreads();
    #pragma unroll
    for (int r = 0; r < 4; r++) {
        int bo = bo0 + ty + 8 * r;
        float bv = bias[(size_t)(bo & 63) * 1024 + pos0 + tx];
        out[(size_t)bo * 1024 + pos0 + tx] = tile[tx][ty + 8 * r] + bv;
    }
}

extern "C" void kernel_launch(void* const* d_in, const int* in_sizes, int n_in,
                              void* d_out, int out_size)
{
    const float* x    = (const float*)d_in[0];
    const float* wgt  = (const float*)d_in[1];
    const float* bias = (const float*)d_in[2];
    float* out        = (float*)d_out;

    cudaFuncSetAttribute(local2d_mma,
                         cudaFuncAttributeMaxDynamicSharedMemorySize, SMEM_BYTES);

    k_zero<<<(64 * 132 * 8 + 255) / 256, 256>>>();
    k_tin<<<dim3(CI_, H_), dim3(32, 8)>>>(x);
    local2d_mma<<<dim3(1024, 2), NT, SMEM_BYTES>>>(wgt);
    k_tout<<<dim3(32, 64), dim3(32, 8)>>>(out, bias);
}